// round 5
// baseline (speedup 1.0000x reference)
#include <cuda_runtime.h>

// ---------------------------------------------------------------------------
// Problem constants
// ---------------------------------------------------------------------------
namespace {
constexpr int NB = 32;       // batch
constexpr int NT = 64;       // decode steps
constexpr int NS = 128;      // source length
constexpr int EH = 512;      // encoder hidden
constexpr int DH = 512;      // decoder hidden
constexpr int NA = 256;      // attention dim
constexpr int NE = 256;      // embedding dim
constexpr int NV = 31999;    // vocab - 1 (FC output width)
constexpr int IND = NE + EH; // 768, GRU input dim
constexpr int NG = 3 * DH;   // 1536 gate rows
constexpr int NKC = 4;       // K-chunks in gate GEMM
constexpr int NBLK = 128;    // persistent-loop blocks (<=148 SMs -> co-resident)
}

// ---------------------------------------------------------------------------
// Device scratch (no allocations allowed)
// ---------------------------------------------------------------------------
__device__ __align__(16) float g_encT[NB * NA * NS];        // enc_proj [b][a][s]
__device__ __align__(16) float g_h[NT * NB * DH];           // h_t for all steps
__device__ __align__(16) float g_ctx[NB * EH];              // per-step context
__device__ __align__(16) float g_epart[NB * 4 * NS];        // energy partials
__device__ __align__(16) float g_wihT[NE * NG];             // W_ih[:, :256] transposed
__device__ __align__(16) float g_gxemb[NT * NG * NB];       // [t][row][b]
__device__ __align__(16) float g_gpart[NKC * 2 * NG * NB];  // [kc][row 0..3071][b]

// global spin barrier state (sense-reversing; replay-safe)
__device__ int g_cnt;
__device__ volatile int g_sense;

// ---------------------------------------------------------------------------
// helpers
// ---------------------------------------------------------------------------
__device__ __forceinline__ unsigned long long pack2(float lo, float hi) {
    unsigned long long r;
    asm("mov.b64 %0, {%1, %2};" : "=l"(r) : "f"(lo), "f"(hi));
    return r;
}
__device__ __forceinline__ void ffma2(unsigned long long& c, unsigned long long a,
                                      unsigned long long b) {
    asm("fma.rn.f32x2 %0, %1, %2, %0;" : "+l"(c) : "l"(a), "l"(b));
}
__device__ __forceinline__ void unpack2(unsigned long long v, float& lo, float& hi) {
    asm("mov.b64 {%0, %1}, %2;" : "=f"(lo), "=f"(hi) : "l"(v));
}
__device__ __forceinline__ float tanh_hw(float x) {
    float y;
    asm("tanh.approx.f32 %0, %1;" : "=f"(y) : "f"(x));
    return y;
}
__device__ __forceinline__ float fast_tanh(float x) {
    float e2 = __expf(2.0f * x);
    return 1.0f - 2.0f / (e2 + 1.0f);
}
__device__ __forceinline__ float fast_sigmoid(float x) {
    return 1.0f / (1.0f + __expf(-x));
}

// grid-wide barrier: all NBLK blocks co-resident -> spin is safe.
// Release: every thread fences its writes, then block arrives via thread 0.
// Acquire: thread 0 fences after observing flip (CCTL.IVALL flushes L1D).
__device__ __forceinline__ void gbar(int& ls) {
    __threadfence();
    __syncthreads();
    if (threadIdx.x == 0) {
        const int target = ls ^ 1;
        const int pos = atomicAdd(&g_cnt, 1);
        if (pos == NBLK - 1) {
            g_cnt = 0;
            __threadfence();
            g_sense = target;
        } else {
            while (g_sense != target) __nanosleep(64);
        }
        __threadfence();
    }
    __syncthreads();
    ls ^= 1;
}

// ---------------------------------------------------------------------------
// K-pre-a: transpose W_ih[:, 0:256] -> g_wihT[256][1536]
// ---------------------------------------------------------------------------
__global__ void k_trih(const float* __restrict__ W_ih) {
    __shared__ float tile[32][33];
    const int n0 = blockIdx.x * 32;
    const int k0 = blockIdx.y * 32;
    const int tx = threadIdx.x & 31;
    const int ty0 = threadIdx.x >> 5;
#pragma unroll
    for (int i = 0; i < 32; i += 8)
        tile[ty0 + i][tx] = W_ih[(size_t)(n0 + ty0 + i) * IND + k0 + tx];
    __syncthreads();
#pragma unroll
    for (int i = 0; i < 32; i += 8)
        g_wihT[(size_t)(k0 + ty0 + i) * NG + n0 + tx] = tile[tx][ty0 + i];
}

// ---------------------------------------------------------------------------
// K-pre-b: enc_projT[b][a][s]
// ---------------------------------------------------------------------------
__global__ void k_encproj(const float* __restrict__ enc,
                          const float* __restrict__ W_enc) {
    const int rs = blockIdx.x;
    const int b = rs >> 7;
    const int s = rs & 127;
    __shared__ float row[EH];
    for (int i = threadIdx.x; i < EH; i += 256) row[i] = enc[rs * EH + i];
    __syncthreads();
    const int a = threadIdx.x;
    float acc0 = 0.f, acc1 = 0.f;
#pragma unroll 8
    for (int h = 0; h < EH; h += 2) {
        acc0 += row[h] * W_enc[h * NA + a];
        acc1 += row[h + 1] * W_enc[(h + 1) * NA + a];
    }
    g_encT[(b * NA + a) * NS + s] = acc0 + acc1;
}

// ---------------------------------------------------------------------------
// K-pre-c: gx_emb[t][n][b] = emb[y[b][t]] . W_ih[n][:256]
// ---------------------------------------------------------------------------
constexpr int FBM = 128, FBN = 128, FBK = 8;

__global__ void __launch_bounds__(256) k_gxemb(const int* __restrict__ y,
                                               const float* __restrict__ embedding) {
    __shared__ __align__(16) float As[FBK][FBM];
    __shared__ __align__(16) float Bs[FBK][FBN];

    const int n0 = blockIdx.x * FBN;
    const int m0 = blockIdx.y * FBM;
    const int tid = threadIdx.x;
    const int tx = tid & 15;
    const int ty = tid >> 4;
    const int am = tid >> 1;
    const int ak4 = (tid & 1) * 4;
    const int bk = tid >> 5;
    const int bn = (tid & 31) * 4;

    const int m = m0 + am;
    const int tok = y[(m & 31) * NT + (m >> 5)];
    const float* arow = embedding + (size_t)tok * NE;

    unsigned long long c2[2][2][2][4];
#pragma unroll
    for (int a = 0; a < 2; a++)
#pragma unroll
        for (int p = 0; p < 2; p++)
#pragma unroll
            for (int h = 0; h < 2; h++)
#pragma unroll
                for (int j = 0; j < 4; j++) c2[a][p][h][j] = 0ull;

    for (int kt = 0; kt < NE; kt += FBK) {
        float4 a4 = *reinterpret_cast<const float4*>(arow + kt + ak4);
        As[ak4 + 0][am] = a4.x;
        As[ak4 + 1][am] = a4.y;
        As[ak4 + 2][am] = a4.z;
        As[ak4 + 3][am] = a4.w;
        float4 b4 = *reinterpret_cast<const float4*>(
            &g_wihT[(size_t)(kt + bk) * NG + n0 + bn]);
        Bs[bk][bn + 0] = b4.x;
        Bs[bk][bn + 1] = b4.y;
        Bs[bk][bn + 2] = b4.z;
        Bs[bk][bn + 3] = b4.w;
        __syncthreads();
#pragma unroll
        for (int kk = 0; kk < FBK; kk++) {
            unsigned long long a2[2][2];
            float4 bv[2];
#pragma unroll
            for (int h = 0; h < 2; h++) {
                float4 av = *reinterpret_cast<const float4*>(&As[kk][h * 64 + ty * 4]);
                a2[h][0] = pack2(av.x, av.y);
                a2[h][1] = pack2(av.z, av.w);
                bv[h] = *reinterpret_cast<const float4*>(&Bs[kk][h * 64 + tx * 4]);
            }
#pragma unroll
            for (int hb = 0; hb < 2; hb++) {
                float bj[4] = {bv[hb].x, bv[hb].y, bv[hb].z, bv[hb].w};
#pragma unroll
                for (int j = 0; j < 4; j++) {
                    unsigned long long b2 = pack2(bj[j], bj[j]);
#pragma unroll
                    for (int ha = 0; ha < 2; ha++)
#pragma unroll
                        for (int ip = 0; ip < 2; ip++)
                            ffma2(c2[ha][ip][hb][j], a2[ha][ip], b2);
                }
            }
        }
        __syncthreads();
    }

#pragma unroll
    for (int ha = 0; ha < 2; ha++)
#pragma unroll
        for (int ip = 0; ip < 2; ip++) {
            const int mm = m0 + ha * 64 + ty * 4 + ip * 2;
            const int tt = mm >> 5, bb = mm & 31;
#pragma unroll
            for (int hb = 0; hb < 2; hb++)
#pragma unroll
                for (int j = 0; j < 4; j++) {
                    const int n = n0 + hb * 64 + tx * 4 + j;
                    float lo, hi;
                    unpack2(c2[ha][ip][hb][j], lo, hi);
                    float2* dst = reinterpret_cast<float2*>(
                        &g_gxemb[((size_t)tt * NG + n) * NB + bb]);
                    *dst = make_float2(lo, hi);
                }
        }
}

// ---------------------------------------------------------------------------
// K-loop: persistent kernel, all 64 steps, 4 phases with grid barriers.
// ---------------------------------------------------------------------------
constexpr int GM = 128;   // gate rows per block
constexpr int GKC = 128;  // K per chunk

struct SA {  // energy phase
    float prev[DH];
    float dpart[4][64];
    float decs[64];
    float vsh[64];
    float ep2[2][NS];
};
struct SB {  // softmax+ctx phase
    float aw[NS];
    float cpart[2][128];
};
struct SC {  // gates phase
    float As[32][GM];
    float Bs[32][36];
};
union SmemU {
    SA a;
    SB b;
    SC c;
};

__global__ void __launch_bounds__(256) k_loop(
        const float* __restrict__ enc,
        const float* __restrict__ dec_init,
        const int* __restrict__ mask,
        const float* __restrict__ W_dec,
        const float* __restrict__ v,
        const float* __restrict__ W_ih,
        const float* __restrict__ W_hh,
        const float* __restrict__ b_ih,
        const float* __restrict__ b_hh,
        float* __restrict__ attn_out) {
    const int blk = blockIdx.x;
    const int tid = threadIdx.x;
    __shared__ SmemU sm;

    int ls = g_sense;  // stable: no barrier fires until all blocks have read it

    for (int t = 0; t < NT; t++) {
        // ---------------- Phase A: energy partials (b = blk>>2, at = blk&3)
        {
            const int b = blk >> 2;
            const int at = blk & 3;
            const int a0 = at * 64;
            const float* pv = (t == 0) ? (dec_init + b * DH)
                                       : (g_h + ((size_t)(t - 1) * NB + b) * DH);
            sm.a.prev[tid] = pv[tid];
            sm.a.prev[tid + 256] = pv[tid + 256];
            if (tid < 64) sm.a.vsh[tid] = v[a0 + tid];
            __syncthreads();

            // A1: dec slice, 16-deep MLP
            {
                const int j = tid & 63;
                const int hq = tid >> 6;
                const float* W0 = W_dec + (size_t)(hq * 128) * NA + a0 + j;
                const float* pr = sm.a.prev + hq * 128;
                float c[16];
#pragma unroll
                for (int u = 0; u < 16; u++) c[u] = 0.f;
#pragma unroll
                for (int h = 0; h < 128; h += 16) {
#pragma unroll
                    for (int u = 0; u < 16; u++)
                        c[u] += pr[h + u] * W0[(h + u) * NA];
                }
                float s0 = 0.f;
#pragma unroll
                for (int u = 0; u < 16; u++) s0 += c[u];
                sm.a.dpart[hq][j] = s0;
            }
            __syncthreads();
            if (tid < 64)
                sm.a.decs[tid] = (sm.a.dpart[0][tid] + sm.a.dpart[1][tid]) +
                                 (sm.a.dpart[2][tid] + sm.a.dpart[3][tid]);
            __syncthreads();

            // A2: energy partial, 8-deep MLP
            {
                const int ah = tid >> 7;
                const int ss = tid & 127;
                const float* et = g_encT + ((size_t)b * NA + a0 + ah * 32) * NS + ss;
                const float* dv = sm.a.decs + ah * 32;
                const float* vv = sm.a.vsh + ah * 32;
                float c[8];
#pragma unroll
                for (int u = 0; u < 8; u++) c[u] = 0.f;
#pragma unroll
                for (int a = 0; a < 32; a += 8) {
#pragma unroll
                    for (int u = 0; u < 8; u++)
                        c[u] += tanh_hw(et[(a + u) * NS] + dv[a + u]) * vv[a + u];
                }
                float s0 = 0.f;
#pragma unroll
                for (int u = 0; u < 8; u++) s0 += c[u];
                sm.a.ep2[ah][ss] = s0;
            }
            __syncthreads();
            if (tid < NS)
                g_epart[((size_t)b * 4 + at) * NS + tid] =
                    sm.a.ep2[0][tid] + sm.a.ep2[1][tid];
        }
        gbar(ls);

        // ---------------- Phase B: softmax + context (b = blk>>2, dt = blk&3)
        {
            const int b = blk >> 2;
            const int dt = blk & 3;
            const int d0 = dt * 128;

            if (tid < 32) {
                float en[4];
#pragma unroll
                for (int j = 0; j < 4; j++) {
                    const int s = tid + j * 32;
                    const float* gp = g_epart + (size_t)(b * 4) * NS + s;
                    float x = (__ldcg(gp) + __ldcg(gp + NS)) +
                              (__ldcg(gp + 2 * NS) + __ldcg(gp + 3 * NS));
                    if (mask[b * NS + s] == 0) x = -1e9f;
                    en[j] = x;
                }
                float mx = fmaxf(fmaxf(en[0], en[1]), fmaxf(en[2], en[3]));
#pragma unroll
                for (int off = 16; off > 0; off >>= 1)
                    mx = fmaxf(mx, __shfl_xor_sync(0xffffffffu, mx, off));
                float sum = 0.f;
#pragma unroll
                for (int j = 0; j < 4; j++) {
                    en[j] = __expf(en[j] - mx);
                    sum += en[j];
                }
#pragma unroll
                for (int off = 16; off > 0; off >>= 1)
                    sum += __shfl_xor_sync(0xffffffffu, sum, off);
                const float inv = 1.0f / sum;
#pragma unroll
                for (int j = 0; j < 4; j++) {
                    const float w = en[j] * inv;
                    sm.b.aw[tid + j * 32] = w;
                    if (dt == 0)
                        attn_out[((size_t)(b * NT + t)) * NS + tid + j * 32] = w;
                }
            }
            __syncthreads();

            {
                const int sh = tid >> 7;
                const int d = d0 + (tid & 127);
                const float* eb = enc + ((size_t)b * NS + sh * 64) * EH + d;
                const float* w = sm.b.aw + sh * 64;
                float c[8];
#pragma unroll
                for (int u = 0; u < 8; u++) c[u] = 0.f;
#pragma unroll
                for (int s = 0; s < 64; s += 8) {
#pragma unroll
                    for (int u = 0; u < 8; u++)
                        c[u] += w[s + u] * eb[(s + u) * EH];
                }
                float s0 = 0.f;
#pragma unroll
                for (int u = 0; u < 8; u++) s0 += c[u];
                sm.b.cpart[sh][tid & 127] = s0;
            }
            __syncthreads();
            if (tid < 128)
                g_ctx[b * EH + d0 + tid] = sm.b.cpart[0][tid] + sm.b.cpart[1][tid];
        }
        gbar(ls);

        // ---------------- Phase C: gate GEMM partials (blocks 0..95)
        if (blk < 96) {
            const int mt = blk >> 2;
            const int kc = blk & 3;
            const int r0 = mt * GM;
            const bool is_ih = (r0 < NG);

            const float* bsrc = is_ih
                ? g_ctx
                : ((t == 0) ? dec_init : (g_h + (size_t)(t - 1) * NB * DH));

            const int rp0 = tid >> 3;
            const int bg = (tid & 7) * 4;

            unsigned long long acc[2][4];
#pragma unroll
            for (int p = 0; p < 2; p++)
#pragma unroll
                for (int j = 0; j < 4; j++) acc[p][j] = 0ull;

            const int ar = tid >> 1;
            const int akq = (tid & 1) * 16;
            const int grow = r0 + ar;
            const float* wrow = is_ih ? (W_ih + (size_t)grow * IND + NE)
                                      : (W_hh + (size_t)(grow - NG) * DH);
            const int bb = tid >> 3;
            const int bk4 = (tid & 7) * 4;

#pragma unroll
            for (int kt = 0; kt < GKC / 32; kt++) {
                const int kg0 = kc * GKC + kt * 32;
#pragma unroll
                for (int q = 0; q < 4; q++) {
                    float4 a4 = *reinterpret_cast<const float4*>(
                        wrow + kg0 + akq + q * 4);
                    sm.c.As[akq + q * 4 + 0][ar] = a4.x;
                    sm.c.As[akq + q * 4 + 1][ar] = a4.y;
                    sm.c.As[akq + q * 4 + 2][ar] = a4.z;
                    sm.c.As[akq + q * 4 + 3][ar] = a4.w;
                }
                {
                    float4 b4 = __ldcg(reinterpret_cast<const float4*>(
                        bsrc + bb * 512 + kg0 + bk4));
                    sm.c.Bs[bk4 + 0][bb] = b4.x;
                    sm.c.Bs[bk4 + 1][bb] = b4.y;
                    sm.c.Bs[bk4 + 2][bb] = b4.z;
                    sm.c.Bs[bk4 + 3][bb] = b4.w;
                }
                __syncthreads();
#pragma unroll
                for (int kk = 0; kk < 32; kk++) {
                    float2 av0 = *reinterpret_cast<const float2*>(
                        &sm.c.As[kk][2 * rp0]);
                    float2 av1 = *reinterpret_cast<const float2*>(
                        &sm.c.As[kk][2 * rp0 + 64]);
                    unsigned long long a20 = pack2(av0.x, av0.y);
                    unsigned long long a21 = pack2(av1.x, av1.y);
                    float4 bv = *reinterpret_cast<const float4*>(&sm.c.Bs[kk][bg]);
                    float bj[4] = {bv.x, bv.y, bv.z, bv.w};
#pragma unroll
                    for (int j = 0; j < 4; j++) {
                        unsigned long long b2 = pack2(bj[j], bj[j]);
                        ffma2(acc[0][j], a20, b2);
                        ffma2(acc[1][j], a21, b2);
                    }
                }
                __syncthreads();
            }

#pragma unroll
            for (int p = 0; p < 2; p++) {
                const int r = r0 + 2 * rp0 + p * 64;
#pragma unroll
                for (int j = 0; j < 4; j++) {
                    float lo, hi;
                    unpack2(acc[p][j], lo, hi);
                    g_gpart[((size_t)kc * 2 * NG + r) * NB + bg + j] = lo;
                    g_gpart[((size_t)kc * 2 * NG + r + 1) * NB + bg + j] = hi;
                }
            }
        }
        gbar(ls);

        // ---------------- Phase D: combine -> h_t  (4 i per block, warps 0-3)
        {
            const int w = tid >> 5;
            const int lane = tid & 31;
            if (w < 4) {
                const int i = blk * 4 + w;
                const int b = lane;
                float gx[3], gh[3];
#pragma unroll
                for (int g = 0; g < 3; g++) {
                    const int R = g * DH + i;
                    float s1 = g_gxemb[((size_t)t * NG + R) * NB + b] + b_ih[R];
                    float s2 = b_hh[R];
#pragma unroll
                    for (int kc = 0; kc < NKC; kc++) {
                        s1 += __ldcg(&g_gpart[((size_t)kc * 2 * NG + R) * NB + b]);
                        s2 += __ldcg(
                            &g_gpart[((size_t)kc * 2 * NG + NG + R) * NB + b]);
                    }
                    gx[g] = s1;
                    gh[g] = s2;
                }
                const float r = fast_sigmoid(gx[0] + gh[0]);
                const float z = fast_sigmoid(gx[1] + gh[1]);
                const float n = fast_tanh(gx[2] + r * gh[2]);
                const float prev = (t == 0)
                    ? dec_init[b * DH + i]
                    : g_h[((size_t)(t - 1) * NB + b) * DH + i];
                g_h[((size_t)t * NB + b) * DH + i] = (1.0f - z) * n + z * prev;
            }
        }
        gbar(ls);
    }
}

// ---------------------------------------------------------------------------
// K-fc: batched FC:  out[(b,t), n] = h_all[(t,b), :] @ W_fc + b_fc
// ---------------------------------------------------------------------------
__global__ void __launch_bounds__(256) k_fc(const float* __restrict__ Wfc,
                                            const float* __restrict__ bfc,
                                            float* __restrict__ out) {
    __shared__ __align__(16) float As[FBK][FBM];
    __shared__ __align__(16) float Bs[FBK][FBN];

    const int n0 = blockIdx.x * FBN;
    const int m0 = blockIdx.y * FBM;
    const int tid = threadIdx.x;
    const int tx = tid & 15;
    const int ty = tid >> 4;
    const int am = tid >> 1;
    const int ak4 = (tid & 1) * 4;
    const int bk = tid >> 5;
    const int bn = (tid & 31) * 4;

    unsigned long long c2[2][2][2][4];
#pragma unroll
    for (int a = 0; a < 2; a++)
#pragma unroll
        for (int p = 0; p < 2; p++)
#pragma unroll
            for (int h = 0; h < 2; h++)
#pragma unroll
                for (int j = 0; j < 4; j++) c2[a][p][h][j] = 0ull;

    for (int kt = 0; kt < DH; kt += FBK) {
        float4 a4 = *reinterpret_cast<const float4*>(
            &g_h[(size_t)(m0 + am) * DH + kt + ak4]);
        As[ak4 + 0][am] = a4.x;
        As[ak4 + 1][am] = a4.y;
        As[ak4 + 2][am] = a4.z;
        As[ak4 + 3][am] = a4.w;
#pragma unroll
        for (int q = 0; q < 4; q++) {
            int n = n0 + bn + q;
            Bs[bk][bn + q] = (n < NV) ? Wfc[(size_t)(kt + bk) * NV + n] : 0.f;
        }
        __syncthreads();

#pragma unroll
        for (int kk = 0; kk < FBK; kk++) {
            unsigned long long a2[2][2];
            float4 bv[2];
#pragma unroll
            for (int h = 0; h < 2; h++) {
                float4 av = *reinterpret_cast<const float4*>(&As[kk][h * 64 + ty * 4]);
                a2[h][0] = pack2(av.x, av.y);
                a2[h][1] = pack2(av.z, av.w);
                bv[h] = *reinterpret_cast<const float4*>(&Bs[kk][h * 64 + tx * 4]);
            }
#pragma unroll
            for (int hb = 0; hb < 2; hb++) {
                float bj[4] = {bv[hb].x, bv[hb].y, bv[hb].z, bv[hb].w};
#pragma unroll
                for (int j = 0; j < 4; j++) {
                    unsigned long long b2 = pack2(bj[j], bj[j]);
#pragma unroll
                    for (int ha = 0; ha < 2; ha++)
#pragma unroll
                        for (int ip = 0; ip < 2; ip++)
                            ffma2(c2[ha][ip][hb][j], a2[ha][ip], b2);
                }
            }
        }
        __syncthreads();
    }

#pragma unroll
    for (int ha = 0; ha < 2; ha++)
#pragma unroll
        for (int ip = 0; ip < 2; ip++) {
            const int m = m0 + ha * 64 + ty * 4 + ip * 2;
#pragma unroll
            for (int hb = 0; hb < 2; hb++)
#pragma unroll
                for (int j = 0; j < 4; j++) {
                    const int n = n0 + hb * 64 + tx * 4 + j;
                    if (n < NV) {
                        float lo, hi;
                        unpack2(c2[ha][ip][hb][j], lo, hi);
                        const float bias = bfc[n];
                        const int t1 = m >> 5, b1 = m & 31;
                        const int t2 = (m + 1) >> 5, b2i = (m + 1) & 31;
                        out[((size_t)(b1 * NT + t1)) * NV + n] = lo + bias;
                        out[((size_t)(b2i * NT + t2)) * NV + n] = hi + bias;
                    }
                }
        }
}

// ---------------------------------------------------------------------------
// Launch
// ---------------------------------------------------------------------------
extern "C" void kernel_launch(void* const* d_in, const int* in_sizes, int n_in,
                              void* d_out, int out_size) {
    const int* y = (const int*)d_in[0];
    const float* enc = (const float*)d_in[1];
    const float* dec_init = (const float*)d_in[2];
    const int* mask = (const int*)d_in[3];
    const float* emb = (const float*)d_in[4];
    const float* W_enc = (const float*)d_in[5];
    const float* W_dec = (const float*)d_in[6];
    const float* v = (const float*)d_in[7];
    const float* W_ih = (const float*)d_in[8];
    const float* W_hh = (const float*)d_in[9];
    const float* b_ih = (const float*)d_in[10];
    const float* b_hh = (const float*)d_in[11];
    const float* W_fc = (const float*)d_in[12];
    const float* b_fc = (const float*)d_in[13];

    float* out = (float*)d_out;
    float* attn_out = out + (size_t)NB * NT * NV;

    k_trih<<<dim3(NG / 32, NE / 32), 256>>>(W_ih);
    k_encproj<<<NB * NS, 256>>>(enc, W_enc);
    k_gxemb<<<dim3(NG / FBN, (NB * NT) / FBM), 256>>>(y, emb);
    k_loop<<<NBLK, 256>>>(enc, dec_init, mask, W_dec, v, W_ih, W_hh,
                          b_ih, b_hh, attn_out);
    dim3 gfc((NV + FBN - 1) / FBN, (NB * NT) / FBM);
    k_fc<<<gfc, 256>>>(W_fc, b_fc, out);
}

// round 6
// speedup vs baseline: 1.0940x; 1.0940x over previous
#include <cuda_runtime.h>

// ---------------------------------------------------------------------------
// Problem constants
// ---------------------------------------------------------------------------
namespace {
constexpr int NB = 32;       // batch
constexpr int NT = 64;       // decode steps
constexpr int NS = 128;      // source length
constexpr int EH = 512;      // encoder hidden
constexpr int DH = 512;      // decoder hidden
constexpr int NA = 256;      // attention dim
constexpr int NE = 256;      // embedding dim
constexpr int NV = 31999;    // vocab - 1 (FC output width)
constexpr int IND = NE + EH; // 768, GRU input dim
constexpr int NG = 3 * DH;   // 1536 gate rows
constexpr int NKC = 4;       // K-chunks in gate GEMM
constexpr int NBLK = 128;    // persistent-loop blocks (<=148 SMs -> co-resident)
}

// ---------------------------------------------------------------------------
// Device scratch (no allocations allowed)
// ---------------------------------------------------------------------------
__device__ __align__(16) float g_encT[NB * NA * NS];        // enc_proj [b][a][s]
__device__ __align__(16) float g_h[NT * NB * DH];           // h_t for all steps
__device__ __align__(16) float g_ctx[NB * EH];              // per-step context
__device__ __align__(16) float g_epart[NB * 4 * NS];        // energy partials
__device__ __align__(16) float g_wihT[NE * NG];             // W_ih[:, :256] transposed
__device__ __align__(16) float g_gxemb[NT * NB * NG];       // [(t,b)][row]
__device__ __align__(16) float g_gpart[NKC * NB * 2 * NG];  // [kc][b][row 0..3071]

// grid barrier counter (cooperative-groups flip-bit pattern; replay-safe)
__device__ unsigned int g_arrive;

// ---------------------------------------------------------------------------
// helpers
// ---------------------------------------------------------------------------
__device__ __forceinline__ unsigned long long pack2(float lo, float hi) {
    unsigned long long r;
    asm("mov.b64 %0, {%1, %2};" : "=l"(r) : "f"(lo), "f"(hi));
    return r;
}
__device__ __forceinline__ void ffma2(unsigned long long& c, unsigned long long a,
                                      unsigned long long b) {
    asm("fma.rn.f32x2 %0, %1, %2, %0;" : "+l"(c) : "l"(a), "l"(b));
}
__device__ __forceinline__ void unpack2(unsigned long long v, float& lo, float& hi) {
    asm("mov.b64 {%0, %1}, %2;" : "=f"(lo), "=f"(hi) : "l"(v));
}
__device__ __forceinline__ float tanh_hw(float x) {
    float y;
    asm("tanh.approx.f32 %0, %1;" : "=f"(y) : "f"(x));
    return y;
}
__device__ __forceinline__ float fast_tanh(float x) {
    float e2 = __expf(2.0f * x);
    return 1.0f - 2.0f / (e2 + 1.0f);
}
__device__ __forceinline__ float fast_sigmoid(float x) {
    return 1.0f / (1.0f + __expf(-x));
}

// grid-wide barrier, cooperative-groups style: fence + counter-flip by ONE
// thread per block (not 256). All NBLK blocks co-resident -> spin is safe.
__device__ __forceinline__ void gbar() {
    __syncthreads();
    if (threadIdx.x == 0) {
        __threadfence();  // release this block's writes
        unsigned int nb = 1;
        if (blockIdx.x == 0) nb = 0x80000000u - (NBLK - 1);
        const unsigned int old = atomicAdd(&g_arrive, nb);
        volatile unsigned int* va = &g_arrive;
        while (((old ^ *va) & 0x80000000u) == 0) {}
        __threadfence();  // acquire (CCTL.IVALL flushes this SM's L1D)
    }
    __syncthreads();
}

// ---------------------------------------------------------------------------
// K-pre-a: transpose W_ih[:, 0:256] -> g_wihT[256][1536]
// ---------------------------------------------------------------------------
__global__ void k_trih(const float* __restrict__ W_ih) {
    __shared__ float tile[32][33];
    const int n0 = blockIdx.x * 32;
    const int k0 = blockIdx.y * 32;
    const int tx = threadIdx.x & 31;
    const int ty0 = threadIdx.x >> 5;
#pragma unroll
    for (int i = 0; i < 32; i += 8)
        tile[ty0 + i][tx] = W_ih[(size_t)(n0 + ty0 + i) * IND + k0 + tx];
    __syncthreads();
#pragma unroll
    for (int i = 0; i < 32; i += 8)
        g_wihT[(size_t)(k0 + ty0 + i) * NG + n0 + tx] = tile[tx][ty0 + i];
}

// ---------------------------------------------------------------------------
// K-pre-b: enc_projT[b][a][s]
// ---------------------------------------------------------------------------
__global__ void k_encproj(const float* __restrict__ enc,
                          const float* __restrict__ W_enc) {
    const int rs = blockIdx.x;
    const int b = rs >> 7;
    const int s = rs & 127;
    __shared__ float row[EH];
    for (int i = threadIdx.x; i < EH; i += 256) row[i] = enc[rs * EH + i];
    __syncthreads();
    const int a = threadIdx.x;
    float acc0 = 0.f, acc1 = 0.f;
#pragma unroll 8
    for (int h = 0; h < EH; h += 2) {
        acc0 += row[h] * W_enc[h * NA + a];
        acc1 += row[h + 1] * W_enc[(h + 1) * NA + a];
    }
    g_encT[(b * NA + a) * NS + s] = acc0 + acc1;
}

// ---------------------------------------------------------------------------
// K-pre-c: gx_emb[(t,b)][n] = emb[y[b][t]] . W_ih[n][:256]
// GEMM M=2048 (m = t*32+b), N=1536, K=256.  Row-major C output.
// ---------------------------------------------------------------------------
constexpr int FBM = 128, FBN = 128, FBK = 8;

__global__ void __launch_bounds__(256) k_gxemb(const int* __restrict__ y,
                                               const float* __restrict__ embedding) {
    __shared__ __align__(16) float As[FBK][FBM];
    __shared__ __align__(16) float Bs[FBK][FBN];

    const int n0 = blockIdx.x * FBN;
    const int m0 = blockIdx.y * FBM;
    const int tid = threadIdx.x;
    const int tx = tid & 15;
    const int ty = tid >> 4;
    const int am = tid >> 1;
    const int ak4 = (tid & 1) * 4;
    const int bk = tid >> 5;
    const int bn = (tid & 31) * 4;

    const int m = m0 + am;
    const int tok = y[(m & 31) * NT + (m >> 5)];
    const float* arow = embedding + (size_t)tok * NE;

    unsigned long long c2[2][2][2][4];
#pragma unroll
    for (int a = 0; a < 2; a++)
#pragma unroll
        for (int p = 0; p < 2; p++)
#pragma unroll
            for (int h = 0; h < 2; h++)
#pragma unroll
                for (int j = 0; j < 4; j++) c2[a][p][h][j] = 0ull;

    for (int kt = 0; kt < NE; kt += FBK) {
        float4 a4 = *reinterpret_cast<const float4*>(arow + kt + ak4);
        As[ak4 + 0][am] = a4.x;
        As[ak4 + 1][am] = a4.y;
        As[ak4 + 2][am] = a4.z;
        As[ak4 + 3][am] = a4.w;
        float4 b4 = *reinterpret_cast<const float4*>(
            &g_wihT[(size_t)(kt + bk) * NG + n0 + bn]);
        Bs[bk][bn + 0] = b4.x;
        Bs[bk][bn + 1] = b4.y;
        Bs[bk][bn + 2] = b4.z;
        Bs[bk][bn + 3] = b4.w;
        __syncthreads();
#pragma unroll
        for (int kk = 0; kk < FBK; kk++) {
            unsigned long long a2[2][2];
            float4 bv[2];
#pragma unroll
            for (int h = 0; h < 2; h++) {
                float4 av = *reinterpret_cast<const float4*>(&As[kk][h * 64 + ty * 4]);
                a2[h][0] = pack2(av.x, av.y);
                a2[h][1] = pack2(av.z, av.w);
                bv[h] = *reinterpret_cast<const float4*>(&Bs[kk][h * 64 + tx * 4]);
            }
#pragma unroll
            for (int hb = 0; hb < 2; hb++) {
                float bj[4] = {bv[hb].x, bv[hb].y, bv[hb].z, bv[hb].w};
#pragma unroll
                for (int j = 0; j < 4; j++) {
                    unsigned long long b2 = pack2(bj[j], bj[j]);
#pragma unroll
                    for (int ha = 0; ha < 2; ha++)
#pragma unroll
                        for (int ip = 0; ip < 2; ip++)
                            ffma2(c2[ha][ip][hb][j], a2[ha][ip], b2);
                }
            }
        }
        __syncthreads();
    }

    // row-major store: g_gxemb[m][n]
#pragma unroll
    for (int ha = 0; ha < 2; ha++)
#pragma unroll
        for (int ip = 0; ip < 2; ip++) {
            const int mm = m0 + ha * 64 + ty * 4 + ip * 2;
#pragma unroll
            for (int hb = 0; hb < 2; hb++) {
                const int n = n0 + hb * 64 + tx * 4;
                float4 lo4, hi4;
                unpack2(c2[ha][ip][hb][0], lo4.x, hi4.x);
                unpack2(c2[ha][ip][hb][1], lo4.y, hi4.y);
                unpack2(c2[ha][ip][hb][2], lo4.z, hi4.z);
                unpack2(c2[ha][ip][hb][3], lo4.w, hi4.w);
                *reinterpret_cast<float4*>(&g_gxemb[(size_t)mm * NG + n]) = lo4;
                *reinterpret_cast<float4*>(&g_gxemb[(size_t)(mm + 1) * NG + n]) = hi4;
            }
        }
}

// ---------------------------------------------------------------------------
// K-loop: persistent kernel, all 64 steps, 3 phases + 3 barriers per step.
// Phase A: combine h_{t-1} from gate partials (dup x4 per b) + energy partials
// Phase B: softmax + context
// Phase C: gate GEMM partials
// ---------------------------------------------------------------------------
constexpr int GM = 128;   // gate rows per block
constexpr int GKC = 128;  // K per chunk

struct SA {  // energy phase
    float dpart[4][64];
    float decs[64];
    float vsh[64];
    float ep2[2][NS];
};
struct SB {  // softmax+ctx phase
    float aw[NS];
    float cpart[2][128];
};
struct SC {  // gates phase
    float As[32][GM];
    float Bs[32][36];
};
union SmemU {
    SA a;
    SB b;
    SC c;
};

__global__ void __launch_bounds__(256) k_loop(
        const float* __restrict__ enc,
        const float* __restrict__ dec_init,
        const int* __restrict__ mask,
        const float* __restrict__ W_dec,
        const float* __restrict__ v,
        const float* __restrict__ W_ih,
        const float* __restrict__ W_hh,
        const float* __restrict__ b_ih,
        const float* __restrict__ b_hh,
        float* __restrict__ attn_out) {
    const int blk = blockIdx.x;
    const int tid = threadIdx.x;
    __shared__ SmemU sm;
    __shared__ __align__(16) float s_prev[DH];  // persists across phases

    const int ab = blk >> 2;   // this block's batch element (A/B phases)
    const int at = blk & 3;    // a-tile / d-tile quadrant

    for (int t = 0; t <= NT; t++) {
        // ---------------- Phase A: combine h_{t-1}, then energy (t < NT)
        if (t == 0) {
            s_prev[tid] = dec_init[ab * DH + tid];
            s_prev[tid + 256] = dec_init[ab * DH + tid + 256];
        } else {
            // combine gate partials -> h_{t-1}; s_prev currently holds h_{t-2}
#pragma unroll
            for (int rep = 0; rep < 2; rep++) {
                const int i = tid + rep * 256;
                float gx[3], gh[3];
#pragma unroll
                for (int g = 0; g < 3; g++) {
                    const int R = g * DH + i;
                    float s1 = g_gxemb[((size_t)(t - 1) * NB + ab) * NG + R]
                               + b_ih[R];
                    float s2 = b_hh[R];
#pragma unroll
                    for (int kc = 0; kc < NKC; kc++) {
                        const float* gp =
                            g_gpart + ((size_t)(kc * NB + ab)) * (2 * NG);
                        s1 += __ldcg(gp + R);
                        s2 += __ldcg(gp + NG + R);
                    }
                    gx[g] = s1;
                    gh[g] = s2;
                }
                const float r = fast_sigmoid(gx[0] + gh[0]);
                const float z = fast_sigmoid(gx[1] + gh[1]);
                const float n = fast_tanh(gx[2] + r * gh[2]);
                const float hn = (1.0f - z) * n + z * s_prev[i];
                s_prev[i] = hn;  // own slot only; no cross-thread hazard
                if (at == 0)
                    g_h[((size_t)(t - 1) * NB + ab) * DH + i] = hn;
            }
        }
        if (t == NT) break;  // tail combine (h_63) done; uniform exit

        {
            const int a0 = at * 64;
            if (tid < 64) sm.a.vsh[tid] = v[a0 + tid];
            __syncthreads();

            // A1: dec slice for 64 a-values, 16-deep MLP
            {
                const int j = tid & 63;
                const int hq = tid >> 6;
                const float* W0 = W_dec + (size_t)(hq * 128) * NA + a0 + j;
                const float* pr = s_prev + hq * 128;
                float c[16];
#pragma unroll
                for (int u = 0; u < 16; u++) c[u] = 0.f;
#pragma unroll
                for (int h = 0; h < 128; h += 16) {
#pragma unroll
                    for (int u = 0; u < 16; u++)
                        c[u] += pr[h + u] * W0[(h + u) * NA];
                }
                float s0 = 0.f;
#pragma unroll
                for (int u = 0; u < 16; u++) s0 += c[u];
                sm.a.dpart[hq][j] = s0;
            }
            __syncthreads();
            if (tid < 64)
                sm.a.decs[tid] = (sm.a.dpart[0][tid] + sm.a.dpart[1][tid]) +
                                 (sm.a.dpart[2][tid] + sm.a.dpart[3][tid]);
            __syncthreads();

            // A2: energy partial, 8-deep MLP
            {
                const int ah = tid >> 7;
                const int ss = tid & 127;
                const float* et =
                    g_encT + ((size_t)ab * NA + a0 + ah * 32) * NS + ss;
                const float* dv = sm.a.decs + ah * 32;
                const float* vv = sm.a.vsh + ah * 32;
                float c[8];
#pragma unroll
                for (int u = 0; u < 8; u++) c[u] = 0.f;
#pragma unroll
                for (int a = 0; a < 32; a += 8) {
#pragma unroll
                    for (int u = 0; u < 8; u++)
                        c[u] += tanh_hw(et[(a + u) * NS] + dv[a + u]) * vv[a + u];
                }
                float s0 = 0.f;
#pragma unroll
                for (int u = 0; u < 8; u++) s0 += c[u];
                sm.a.ep2[ah][ss] = s0;
            }
            __syncthreads();
            if (tid < NS)
                g_epart[((size_t)ab * 4 + at) * NS + tid] =
                    sm.a.ep2[0][tid] + sm.a.ep2[1][tid];
        }
        gbar();

        // ---------------- Phase B: softmax + context (b = ab, dt = at)
        {
            const int d0 = at * 128;

            if (tid < 32) {
                float en[4];
#pragma unroll
                for (int j = 0; j < 4; j++) {
                    const int s = tid + j * 32;
                    const float* gp = g_epart + (size_t)(ab * 4) * NS + s;
                    float x = (__ldcg(gp) + __ldcg(gp + NS)) +
                              (__ldcg(gp + 2 * NS) + __ldcg(gp + 3 * NS));
                    if (mask[ab * NS + s] == 0) x = -1e9f;
                    en[j] = x;
                }
                float mx = fmaxf(fmaxf(en[0], en[1]), fmaxf(en[2], en[3]));
#pragma unroll
                for (int off = 16; off > 0; off >>= 1)
                    mx = fmaxf(mx, __shfl_xor_sync(0xffffffffu, mx, off));
                float sum = 0.f;
#pragma unroll
                for (int j = 0; j < 4; j++) {
                    en[j] = __expf(en[j] - mx);
                    sum += en[j];
                }
#pragma unroll
                for (int off = 16; off > 0; off >>= 1)
                    sum += __shfl_xor_sync(0xffffffffu, sum, off);
                const float inv = 1.0f / sum;
#pragma unroll
                for (int j = 0; j < 4; j++) {
                    const float w = en[j] * inv;
                    sm.b.aw[tid + j * 32] = w;
                    if (at == 0)
                        attn_out[((size_t)(ab * NT + t)) * NS + tid + j * 32] = w;
                }
            }
            __syncthreads();

            {
                const int sh = tid >> 7;
                const int d = d0 + (tid & 127);
                const float* eb = enc + ((size_t)ab * NS + sh * 64) * EH + d;
                const float* w = sm.b.aw + sh * 64;
                float c[8];
#pragma unroll
                for (int u = 0; u < 8; u++) c[u] = 0.f;
#pragma unroll
                for (int s = 0; s < 64; s += 8) {
#pragma unroll
                    for (int u = 0; u < 8; u++)
                        c[u] += w[s + u] * eb[(s + u) * EH];
                }
                float s0 = 0.f;
#pragma unroll
                for (int u = 0; u < 8; u++) s0 += c[u];
                sm.b.cpart[sh][tid & 127] = s0;
            }
            __syncthreads();
            if (tid < 128)
                g_ctx[ab * EH + d0 + tid] = sm.b.cpart[0][tid] + sm.b.cpart[1][tid];
        }
        gbar();

        // ---------------- Phase C: gate GEMM partials (blocks 0..95)
        if (blk < 96) {
            const int mt = blk >> 2;
            const int kc = blk & 3;
            const int r0 = mt * GM;
            const bool is_ih = (r0 < NG);

            const float* bsrc = is_ih
                ? g_ctx
                : ((t == 0) ? dec_init : (g_h + (size_t)(t - 1) * NB * DH));

            const int rp0 = tid >> 3;
            const int bg = (tid & 7) * 4;

            unsigned long long acc[2][4];
#pragma unroll
            for (int p = 0; p < 2; p++)
#pragma unroll
                for (int j = 0; j < 4; j++) acc[p][j] = 0ull;

            const int ar = tid >> 1;
            const int akq = (tid & 1) * 16;
            const int grow = r0 + ar;
            const float* wrow = is_ih ? (W_ih + (size_t)grow * IND + NE)
                                      : (W_hh + (size_t)(grow - NG) * DH);
            const int bb = tid >> 3;
            const int bk4 = (tid & 7) * 4;

#pragma unroll
            for (int kt = 0; kt < GKC / 32; kt++) {
                const int kg0 = kc * GKC + kt * 32;
#pragma unroll
                for (int q = 0; q < 4; q++) {
                    float4 a4 = *reinterpret_cast<const float4*>(
                        wrow + kg0 + akq + q * 4);
                    sm.c.As[akq + q * 4 + 0][ar] = a4.x;
                    sm.c.As[akq + q * 4 + 1][ar] = a4.y;
                    sm.c.As[akq + q * 4 + 2][ar] = a4.z;
                    sm.c.As[akq + q * 4 + 3][ar] = a4.w;
                }
                {
                    float4 b4 = __ldcg(reinterpret_cast<const float4*>(
                        bsrc + bb * 512 + kg0 + bk4));
                    sm.c.Bs[bk4 + 0][bb] = b4.x;
                    sm.c.Bs[bk4 + 1][bb] = b4.y;
                    sm.c.Bs[bk4 + 2][bb] = b4.z;
                    sm.c.Bs[bk4 + 3][bb] = b4.w;
                }
                __syncthreads();
#pragma unroll
                for (int kk = 0; kk < 32; kk++) {
                    float2 av0 = *reinterpret_cast<const float2*>(
                        &sm.c.As[kk][2 * rp0]);
                    float2 av1 = *reinterpret_cast<const float2*>(
                        &sm.c.As[kk][2 * rp0 + 64]);
                    unsigned long long a20 = pack2(av0.x, av0.y);
                    unsigned long long a21 = pack2(av1.x, av1.y);
                    float4 bv = *reinterpret_cast<const float4*>(&sm.c.Bs[kk][bg]);
                    float bj[4] = {bv.x, bv.y, bv.z, bv.w};
#pragma unroll
                    for (int j = 0; j < 4; j++) {
                        unsigned long long b2 = pack2(bj[j], bj[j]);
                        ffma2(acc[0][j], a20, b2);
                        ffma2(acc[1][j], a21, b2);
                    }
                }
                __syncthreads();
            }

            // write partials: g_gpart[kc][b][row], row pairs contiguous
#pragma unroll
            for (int p = 0; p < 2; p++) {
                const int r = r0 + 2 * rp0 + p * 64;
#pragma unroll
                for (int j = 0; j < 4; j++) {
                    float lo, hi;
                    unpack2(acc[p][j], lo, hi);
                    *reinterpret_cast<float2*>(
                        &g_gpart[((size_t)(kc * NB + bg + j)) * (2 * NG) + r]) =
                        make_float2(lo, hi);
                }
            }
        }
        gbar();
    }
}

// ---------------------------------------------------------------------------
// K-fc: batched FC:  out[(b,t), n] = h_all[(t,b), :] @ W_fc + b_fc
// ---------------------------------------------------------------------------
__global__ void __launch_bounds__(256) k_fc(const float* __restrict__ Wfc,
                                            const float* __restrict__ bfc,
                                            float* __restrict__ out) {
    __shared__ __align__(16) float As[FBK][FBM];
    __shared__ __align__(16) float Bs[FBK][FBN];

    const int n0 = blockIdx.x * FBN;
    const int m0 = blockIdx.y * FBM;
    const int tid = threadIdx.x;
    const int tx = tid & 15;
    const int ty = tid >> 4;
    const int am = tid >> 1;
    const int ak4 = (tid & 1) * 4;
    const int bk = tid >> 5;
    const int bn = (tid & 31) * 4;

    unsigned long long c2[2][2][2][4];
#pragma unroll
    for (int a = 0; a < 2; a++)
#pragma unroll
        for (int p = 0; p < 2; p++)
#pragma unroll
            for (int h = 0; h < 2; h++)
#pragma unroll
                for (int j = 0; j < 4; j++) c2[a][p][h][j] = 0ull;

    for (int kt = 0; kt < DH; kt += FBK) {
        float4 a4 = *reinterpret_cast<const float4*>(
            &g_h[(size_t)(m0 + am) * DH + kt + ak4]);
        As[ak4 + 0][am] = a4.x;
        As[ak4 + 1][am] = a4.y;
        As[ak4 + 2][am] = a4.z;
        As[ak4 + 3][am] = a4.w;
#pragma unroll
        for (int q = 0; q < 4; q++) {
            int n = n0 + bn + q;
            Bs[bk][bn + q] = (n < NV) ? Wfc[(size_t)(kt + bk) * NV + n] : 0.f;
        }
        __syncthreads();

#pragma unroll
        for (int kk = 0; kk < FBK; kk++) {
            unsigned long long a2[2][2];
            float4 bv[2];
#pragma unroll
            for (int h = 0; h < 2; h++) {
                float4 av = *reinterpret_cast<const float4*>(&As[kk][h * 64 + ty * 4]);
                a2[h][0] = pack2(av.x, av.y);
                a2[h][1] = pack2(av.z, av.w);
                bv[h] = *reinterpret_cast<const float4*>(&Bs[kk][h * 64 + tx * 4]);
            }
#pragma unroll
            for (int hb = 0; hb < 2; hb++) {
                float bj[4] = {bv[hb].x, bv[hb].y, bv[hb].z, bv[hb].w};
#pragma unroll
                for (int j = 0; j < 4; j++) {
                    unsigned long long b2 = pack2(bj[j], bj[j]);
#pragma unroll
                    for (int ha = 0; ha < 2; ha++)
#pragma unroll
                        for (int ip = 0; ip < 2; ip++)
                            ffma2(c2[ha][ip][hb][j], a2[ha][ip], b2);
                }
            }
        }
        __syncthreads();
    }

#pragma unroll
    for (int ha = 0; ha < 2; ha++)
#pragma unroll
        for (int ip = 0; ip < 2; ip++) {
            const int m = m0 + ha * 64 + ty * 4 + ip * 2;
#pragma unroll
            for (int hb = 0; hb < 2; hb++)
#pragma unroll
                for (int j = 0; j < 4; j++) {
                    const int n = n0 + hb * 64 + tx * 4 + j;
                    if (n < NV) {
                        float lo, hi;
                        unpack2(c2[ha][ip][hb][j], lo, hi);
                        const float bias = bfc[n];
                        const int t1 = m >> 5, b1 = m & 31;
                        const int t2 = (m + 1) >> 5, b2i = (m + 1) & 31;
                        out[((size_t)(b1 * NT + t1)) * NV + n] = lo + bias;
                        out[((size_t)(b2i * NT + t2)) * NV + n] = hi + bias;
                    }
                }
        }
}

// ---------------------------------------------------------------------------
// Launch
// ---------------------------------------------------------------------------
extern "C" void kernel_launch(void* const* d_in, const int* in_sizes, int n_in,
                              void* d_out, int out_size) {
    const int* y = (const int*)d_in[0];
    const float* enc = (const float*)d_in[1];
    const float* dec_init = (const float*)d_in[2];
    const int* mask = (const int*)d_in[3];
    const float* emb = (const float*)d_in[4];
    const float* W_enc = (const float*)d_in[5];
    const float* W_dec = (const float*)d_in[6];
    const float* v = (const float*)d_in[7];
    const float* W_ih = (const float*)d_in[8];
    const float* W_hh = (const float*)d_in[9];
    const float* b_ih = (const float*)d_in[10];
    const float* b_hh = (const float*)d_in[11];
    const float* W_fc = (const float*)d_in[12];
    const float* b_fc = (const float*)d_in[13];

    float* out = (float*)d_out;
    float* attn_out = out + (size_t)NB * NT * NV;

    k_trih<<<dim3(NG / 32, NE / 32), 256>>>(W_ih);
    k_encproj<<<NB * NS, 256>>>(enc, W_enc);
    k_gxemb<<<dim3(NG / FBN, (NB * NT) / FBM), 256>>>(y, emb);
    k_loop<<<NBLK, 256>>>(enc, dec_init, mask, W_dec, v, W_ih, W_hh,
                          b_ih, b_hh, attn_out);
    dim3 gfc((NV + FBN - 1) / FBN, (NB * NT) / FBM);
    k_fc<<<gfc, 256>>>(W_fc, b_fc, out);
}